// round 7
// baseline (speedup 1.0000x reference)
#include <cuda_runtime.h>
#include <cstdint>

#define B_   4
#define L_   1024
#define D_   1280
#define H_   20
#define DH_  64
#define BH_  80
#define ALPHA_ 0.48f
#define LOG2E_ 1.44269504088896340736f
#define QSCALE_ (0.125f * LOG2E_)   // fold 1/sqrt(dh) and log2e into Q

// ---------------------------------------------------------------------------
// Scratch (device globals — no allocation allowed)
// ---------------------------------------------------------------------------
__device__ float g_q[BH_ * L_ * DH_];     // tf32-rounded, QSCALE folded
__device__ float g_k[BH_ * L_ * DH_];     // tf32-rounded
__device__ float g_v[BH_ * L_ * DH_];     // tf32-rounded
__device__ float g_kbg[BH_ * L_ * DH_];   // tf32(ALPHA*Kbg)
__device__ float g_vbg[BH_ * L_ * DH_];   // tf32(ALPHA*Vbg)
__device__ float g_xr[B_ * L_ * D_];      // tf32(X)
__device__ float g_ctx[B_ * L_ * D_];     // tf32-rounded context
__device__ float g_wt[4 * D_ * D_];       // tf32(W^T)  [N,K] row-major

// ---------------------------------------------------------------------------
// Helpers (baseline PTX only)
// ---------------------------------------------------------------------------
__device__ __forceinline__ uint32_t smem_to_u32(const void* p) {
  uint32_t a;
  asm("{ .reg .u64 t; cvta.to.shared.u64 t, %1; cvt.u32.u64 %0, t; }"
      : "=r"(a) : "l"(p));
  return a;
}
__device__ __forceinline__ float f2tf_f(float x) {
  uint32_t r;
  asm("cvt.rna.tf32.f32 %0, %1;" : "=r"(r) : "f"(x));
  return __uint_as_float(r);
}
__device__ __forceinline__ float ex2(float x) {
  float r;
  asm("ex2.approx.ftz.f32 %0, %1;" : "=f"(r) : "f"(x));
  return r;
}
__device__ __forceinline__ void mma_tf32(float* c, uint32_t a0, uint32_t a1,
                                         uint32_t a2, uint32_t a3, uint32_t b0,
                                         uint32_t b1) {
  asm volatile(
      "mma.sync.aligned.m16n8k8.row.col.f32.tf32.tf32.f32 "
      "{%0,%1,%2,%3}, {%4,%5,%6,%7}, {%8,%9}, {%0,%1,%2,%3};"
      : "+f"(c[0]), "+f"(c[1]), "+f"(c[2]), "+f"(c[3])
      : "r"(a0), "r"(a1), "r"(a2), "r"(a3), "r"(b0), "r"(b1));
}
__device__ __forceinline__ void cp_async16(uint32_t saddr, const void* g) {
  asm volatile("cp.async.cg.shared.global [%0], [%1], 16;" ::"r"(saddr),
               "l"(g));
}
#define CP_COMMIT() asm volatile("cp.async.commit_group;")
#define CP_WAIT(n) asm volatile("cp.async.wait_group %0;" ::"n"(n))

// ---------------------------------------------------------------------------
// Prep 1: round X -> g_xr; prescale+round bg K/V. All three are 5,242,880 elts.
// ---------------------------------------------------------------------------
__global__ __launch_bounds__(256) void prep_round(const float* __restrict__ X,
                                                  const float* __restrict__ Kbg,
                                                  const float* __restrict__ Vbg) {
  const size_t i = ((size_t)blockIdx.x * 256 + threadIdx.x) * 4;
  {
    const float4 v = *(const float4*)&X[i];
    float4 o;
    o.x = f2tf_f(v.x); o.y = f2tf_f(v.y); o.z = f2tf_f(v.z); o.w = f2tf_f(v.w);
    *(float4*)&g_xr[i] = o;
  }
  {
    const float4 v = *(const float4*)&Kbg[i];
    float4 o;
    o.x = f2tf_f(v.x * ALPHA_); o.y = f2tf_f(v.y * ALPHA_);
    o.z = f2tf_f(v.z * ALPHA_); o.w = f2tf_f(v.w * ALPHA_);
    *(float4*)&g_kbg[i] = o;
  }
  {
    const float4 v = *(const float4*)&Vbg[i];
    float4 o;
    o.x = f2tf_f(v.x * ALPHA_); o.y = f2tf_f(v.y * ALPHA_);
    o.z = f2tf_f(v.z * ALPHA_); o.w = f2tf_f(v.w * ALPHA_);
    *(float4*)&g_vbg[i] = o;
  }
}

// ---------------------------------------------------------------------------
// Prep 2: transpose + round weights: g_wt[z][n][k] = tf32(W_z[k][n])
// ---------------------------------------------------------------------------
__global__ void transpose_w(const float* __restrict__ Wq,
                            const float* __restrict__ Wk,
                            const float* __restrict__ Wv,
                            const float* __restrict__ Wo) {
  __shared__ float t[32][33];
  const float* src;
  switch (blockIdx.z) {
    case 0: src = Wq; break;
    case 1: src = Wk; break;
    case 2: src = Wv; break;
    default: src = Wo; break;
  }
  float* dst = g_wt + (size_t)blockIdx.z * D_ * D_;
  const int x0 = blockIdx.x * 32;  // n
  const int y0 = blockIdx.y * 32;  // k
  const int tx = threadIdx.x;
#pragma unroll
  for (int i = threadIdx.y; i < 32; i += 8)
    t[i][tx] = src[(size_t)(y0 + i) * D_ + x0 + tx];
  __syncthreads();
#pragma unroll
  for (int i = threadIdx.y; i < 32; i += 8)
    dst[(size_t)(x0 + i) * D_ + y0 + tx] = f2tf_f(t[tx][i]);
}

// ---------------------------------------------------------------------------
// tf32 mma GEMM, pre-rounded operands. Block 256 thr (8 warps, 2x4),
// block tile 128x256, warp tile 64x64, K-chunk 32, cp.async double buffer.
// MODE 0: merged QKV -> head layout (Q scaled+rounded, K/V rounded).
// MODE 1: out-proj  -> row-major + bias (fp32).
// ---------------------------------------------------------------------------
#define GM_STR 36
#define GM_ABUF (128 * GM_STR)   // 4608 floats
#define GM_BBUF (256 * GM_STR)   // 9216 floats
#define GM_SMEM_BYTES ((2 * GM_ABUF + 2 * GM_BBUF) * 4)  // 110592

template <int MODE>
__device__ __forceinline__ void gemm_body(const float* __restrict__ A,
                                          const float* __restrict__ Bm,
                                          const float* __restrict__ bo,
                                          float* __restrict__ dstArg) {
  extern __shared__ float sm[];
  float* Abuf[2] = {sm, sm + GM_ABUF};
  float* Bbuf[2] = {sm + 2 * GM_ABUF, sm + 2 * GM_ABUF + GM_BBUF};
  const uint32_t sbase = smem_to_u32(sm);
  const uint32_t aoff[2] = {0u, (uint32_t)(GM_ABUF * 4)};
  const uint32_t boff[2] = {(uint32_t)(2 * GM_ABUF * 4),
                            (uint32_t)((2 * GM_ABUF + GM_BBUF) * 4)};

  const int tid = threadIdx.x;
  const int wid = tid >> 5, lid = tid & 31;
  const int wm = wid >> 2, wn = wid & 3;  // 2 x 4 warps
  const int g = lid >> 2, t = lid & 3;
  const int m0 = blockIdx.y * 128;

  const int ldr = tid >> 3;       // 0..31
  const int ldc = (tid & 7) * 4;  // 0..28

  float c[4][8][4];
#pragma unroll
  for (int ma = 0; ma < 4; ma++)
#pragma unroll
    for (int na = 0; na < 8; na++)
#pragma unroll
      for (int k = 0; k < 4; k++) c[ma][na][k] = 0.f;

  // prologue prefetch chunk 0
#pragma unroll
  for (int i = 0; i < 4; i++) {
    const int r = i * 32 + ldr;
    cp_async16(sbase + aoff[0] + ((r * GM_STR + ldc) << 2),
               &A[(size_t)(m0 + r) * D_ + ldc]);
  }
#pragma unroll
  for (int i = 0; i < 8; i++) {
    const int r = i * 32 + ldr;
    cp_async16(sbase + boff[0] + ((r * GM_STR + ldc) << 2),
               &Bm[(size_t)r * D_ + ldc]);
  }
  CP_COMMIT();

  for (int ch = 0; ch < 40; ch++) {
    const int buf = ch & 1;
    if (ch + 1 < 40) {
      const int nb = 1 - buf;
      const int k0 = (ch + 1) * 32;
#pragma unroll
      for (int i = 0; i < 4; i++) {
        const int r = i * 32 + ldr;
        cp_async16(sbase + aoff[nb] + ((r * GM_STR + ldc) << 2),
                   &A[(size_t)(m0 + r) * D_ + k0 + ldc]);
      }
#pragma unroll
      for (int i = 0; i < 8; i++) {
        const int r = i * 32 + ldr;
        cp_async16(sbase + boff[nb] + ((r * GM_STR + ldc) << 2),
                   &Bm[(size_t)r * D_ + k0 + ldc]);
      }
      CP_COMMIT();
      CP_WAIT(1);
    } else {
      CP_WAIT(0);
    }
    __syncthreads();

    const float* Ab = Abuf[buf];
    const float* Bb = Bbuf[buf];
#pragma unroll
    for (int ks = 0; ks < 4; ks++) {
      uint32_t af[4][4];
#pragma unroll
      for (int ma = 0; ma < 4; ma++) {
        const int row = wm * 64 + ma * 16;
        af[ma][0] = __float_as_uint(Ab[(row + g) * GM_STR + ks * 8 + t]);
        af[ma][1] = __float_as_uint(Ab[(row + g + 8) * GM_STR + ks * 8 + t]);
        af[ma][2] = __float_as_uint(Ab[(row + g) * GM_STR + ks * 8 + t + 4]);
        af[ma][3] = __float_as_uint(Ab[(row + g + 8) * GM_STR + ks * 8 + t + 4]);
      }
      uint32_t bf[8][2];
#pragma unroll
      for (int na = 0; na < 8; na++) {
        const int col = wn * 64 + na * 8 + g;
        bf[na][0] = __float_as_uint(Bb[col * GM_STR + ks * 8 + t]);
        bf[na][1] = __float_as_uint(Bb[col * GM_STR + ks * 8 + t + 4]);
      }
#pragma unroll
      for (int ma = 0; ma < 4; ma++)
#pragma unroll
        for (int na = 0; na < 8; na++)
          mma_tf32(c[ma][na], af[ma][0], af[ma][1], af[ma][2], af[ma][3],
                   bf[na][0], bf[na][1]);
    }
    __syncthreads();
  }

  // epilogue
  if (MODE == 0) {
    const int gn0 = blockIdx.x * 256;
    const int z = gn0 / D_;
    const int nloc0 = gn0 % D_;
    float* dst = (z == 0) ? g_q : (z == 1) ? g_k : g_v;
    const float sc = (z == 0) ? QSCALE_ : 1.f;
#pragma unroll
    for (int ma = 0; ma < 4; ma++) {
      const int r0 = m0 + wm * 64 + ma * 16 + g;
      const int r1 = r0 + 8;
      const int b0i = r0 >> 10, l0i = r0 & 1023;
      const int b1i = r1 >> 10, l1i = r1 & 1023;
#pragma unroll
      for (int na = 0; na < 8; na++) {
        const int col = nloc0 + wn * 64 + na * 8 + 2 * t;
        const int h = col >> 6, dh = col & 63;
        float2 v;
        v.x = f2tf_f(c[ma][na][0] * sc);
        v.y = f2tf_f(c[ma][na][1] * sc);
        *(float2*)&dst[((size_t)(b0i * H_ + h) * L_ + l0i) * DH_ + dh] = v;
        v.x = f2tf_f(c[ma][na][2] * sc);
        v.y = f2tf_f(c[ma][na][3] * sc);
        *(float2*)&dst[((size_t)(b1i * H_ + h) * L_ + l1i) * DH_ + dh] = v;
      }
    }
  } else {
    const int n0 = blockIdx.x * 256;
#pragma unroll
    for (int ma = 0; ma < 4; ma++) {
      const int r0 = m0 + wm * 64 + ma * 16 + g;
      const int r1 = r0 + 8;
#pragma unroll
      for (int na = 0; na < 8; na++) {
        const int col = n0 + wn * 64 + na * 8 + 2 * t;
        const float2 bias = *(const float2*)&bo[col];
        float2 v;
        v.x = c[ma][na][0] + bias.x;
        v.y = c[ma][na][1] + bias.y;
        *(float2*)&dstArg[(size_t)r0 * D_ + col] = v;
        v.x = c[ma][na][2] + bias.x;
        v.y = c[ma][na][3] + bias.y;
        *(float2*)&dstArg[(size_t)r1 * D_ + col] = v;
      }
    }
  }
}

// grid (15, 32): x covers 3840 output cols (Q|K|V), each block inside one W
__global__ __launch_bounds__(256, 1) void gemm_qkv() {
  const int gn0 = blockIdx.x * 256;
  const int z = gn0 / D_;
  const float* Bm = g_wt + (size_t)z * D_ * D_ + (size_t)(gn0 % D_) * D_;
  gemm_body<0>(g_xr, Bm, nullptr, nullptr);
}

// grid (5, 32)
__global__ __launch_bounds__(256, 1) void gemm_out(const float* __restrict__ bo,
                                                   float* __restrict__ out) {
  const float* Bm = g_wt + (size_t)3 * D_ * D_ + (size_t)(blockIdx.x * 256) * D_;
  gemm_body<1>(g_ctx, Bm, bo, out);
}

// ---------------------------------------------------------------------------
// Flash attention, tf32 mma, pre-rounded/pre-scaled inputs.
// Block 256 thr (8 warps), Q tile 128 (16 rows/warp), KV tile 64,
// cp.async double-buffered K/V. grid = (8, 80).
// ---------------------------------------------------------------------------
#define AS 68

__global__ __launch_bounds__(256, 1) void attn_mma() {
  extern __shared__ float sm[];
  float* Qs = sm;                        // 128 x 68
  float* Ps = sm + 128 * AS;             // 128 x 68
  float* Ks[2] = {sm + 2 * 128 * AS, sm + 2 * 128 * AS + 64 * AS};
  float* Vs[2] = {sm + 2 * 128 * AS + 2 * 64 * AS,
                  sm + 2 * 128 * AS + 3 * 64 * AS};
  const uint32_t sbase = smem_to_u32(sm);
  const uint32_t koff[2] = {(uint32_t)(2 * 128 * AS * 4),
                            (uint32_t)((2 * 128 * AS + 64 * AS) * 4)};
  const uint32_t voff[2] = {(uint32_t)((2 * 128 * AS + 2 * 64 * AS) * 4),
                            (uint32_t)((2 * 128 * AS + 3 * 64 * AS) * 4)};

  const int tid = threadIdx.x;
  const int wid = tid >> 5, lid = tid & 31;
  const int g = lid >> 2, t = lid & 3;
  const int bh = blockIdx.y;
  const int q0 = blockIdx.x * 128;

  const float* qptr = g_q + (size_t)bh * L_ * DH_ + (size_t)q0 * DH_;
  const float* kfr = g_k + (size_t)bh * L_ * DH_;
  const float* vfr = g_v + (size_t)bh * L_ * DH_;
  const float* kbg = g_kbg + (size_t)bh * L_ * DH_;
  const float* vbg = g_vbg + (size_t)bh * L_ * DH_;

  // Load Q tile (already scaled+rounded): 128x64 floats
#pragma unroll
  for (int i = 0; i < 8; i++) {
    const int idx = i * 256 + tid;       // float4 index
    const int r = idx >> 4, cc = (idx & 15) * 4;
    *(float4*)&Qs[r * AS + cc] = *(const float4*)&qptr[(size_t)r * DH_ + cc];
  }

  // prefetch KV tile 0
  {
    const int idx = tid;  // reused below
#pragma unroll
    for (int i = 0; i < 4; i++) {
      const int id4 = i * 256 + tid;
      const int r = id4 >> 4, cc = (id4 & 15) * 4;
      cp_async16(sbase + koff[0] + ((r * AS + cc) << 2),
                 &kfr[(size_t)r * DH_ + cc]);
      cp_async16(sbase + voff[0] + ((r * AS + cc) << 2),
                 &vfr[(size_t)r * DH_ + cc]);
    }
    (void)idx;
    CP_COMMIT();
  }

  float mrow[2] = {-1e30f, -1e30f};
  float lrow[2] = {0.f, 0.f};
  float O[8][4];
#pragma unroll
  for (int na = 0; na < 8; na++)
#pragma unroll
    for (int k = 0; k < 4; k++) O[na][k] = 0.f;

  const int pr = wid * 16;  // warp's Q/P row base

  for (int it = 0; it < 32; it++) {
    const int buf = it & 1;
    if (it + 1 < 32) {
      const int nb = 1 - buf;
      const int nt = it + 1;
      const float* kp = (nt < 16) ? kfr + (size_t)nt * 64 * DH_
                                  : kbg + (size_t)(nt - 16) * 64 * DH_;
      const float* vp = (nt < 16) ? vfr + (size_t)nt * 64 * DH_
                                  : vbg + (size_t)(nt - 16) * 64 * DH_;
#pragma unroll
      for (int i = 0; i < 4; i++) {
        const int id4 = i * 256 + tid;
        const int r = id4 >> 4, cc = (id4 & 15) * 4;
        cp_async16(sbase + koff[nb] + ((r * AS + cc) << 2),
                   &kp[(size_t)r * DH_ + cc]);
        cp_async16(sbase + voff[nb] + ((r * AS + cc) << 2),
                   &vp[(size_t)r * DH_ + cc]);
      }
      CP_COMMIT();
      CP_WAIT(1);
    } else {
      CP_WAIT(0);
    }
    __syncthreads();

    const float* Kb = Ks[buf];
    const float* Vb = Vs[buf];

    // S = Q @ K^T : warp rows [pr, pr+16), cols [0,64)
    float s[8][4];
#pragma unroll
    for (int na = 0; na < 8; na++)
#pragma unroll
      for (int k = 0; k < 4; k++) s[na][k] = 0.f;

#pragma unroll
    for (int ks = 0; ks < 8; ks++) {
      const uint32_t a0 = __float_as_uint(Qs[(pr + g) * AS + ks * 8 + t]);
      const uint32_t a1 = __float_as_uint(Qs[(pr + g + 8) * AS + ks * 8 + t]);
      const uint32_t a2 = __float_as_uint(Qs[(pr + g) * AS + ks * 8 + t + 4]);
      const uint32_t a3 = __float_as_uint(Qs[(pr + g + 8) * AS + ks * 8 + t + 4]);
#pragma unroll
      for (int na = 0; na < 8; na++) {
        const uint32_t b0 = __float_as_uint(Kb[(na * 8 + g) * AS + ks * 8 + t]);
        const uint32_t b1 =
            __float_as_uint(Kb[(na * 8 + g) * AS + ks * 8 + t + 4]);
        mma_tf32(s[na], a0, a1, a2, a3, b0, b1);
      }
    }

    // Online softmax (log2 domain)
    float mx0 = -1e30f, mx1 = -1e30f;
#pragma unroll
    for (int na = 0; na < 8; na++) {
      mx0 = fmaxf(mx0, fmaxf(s[na][0], s[na][1]));
      mx1 = fmaxf(mx1, fmaxf(s[na][2], s[na][3]));
    }
    mx0 = fmaxf(mx0, __shfl_xor_sync(0xffffffffu, mx0, 1));
    mx0 = fmaxf(mx0, __shfl_xor_sync(0xffffffffu, mx0, 2));
    mx1 = fmaxf(mx1, __shfl_xor_sync(0xffffffffu, mx1, 1));
    mx1 = fmaxf(mx1, __shfl_xor_sync(0xffffffffu, mx1, 2));

    const float nm0 = fmaxf(mrow[0], mx0);
    const float nm1 = fmaxf(mrow[1], mx1);
    const float corr0 = ex2(mrow[0] - nm0);
    const float corr1 = ex2(mrow[1] - nm1);

    float sum0 = 0.f, sum1 = 0.f;
#pragma unroll
    for (int na = 0; na < 8; na++) {
      s[na][0] = ex2(s[na][0] - nm0);
      s[na][1] = ex2(s[na][1] - nm0);
      s[na][2] = ex2(s[na][2] - nm1);
      s[na][3] = ex2(s[na][3] - nm1);
      sum0 += s[na][0] + s[na][1];
      sum1 += s[na][2] + s[na][3];
    }
    sum0 += __shfl_xor_sync(0xffffffffu, sum0, 1);
    sum0 += __shfl_xor_sync(0xffffffffu, sum0, 2);
    sum1 += __shfl_xor_sync(0xffffffffu, sum1, 1);
    sum1 += __shfl_xor_sync(0xffffffffu, sum1, 2);

    lrow[0] = lrow[0] * corr0 + sum0;
    lrow[1] = lrow[1] * corr1 + sum1;
    mrow[0] = nm0;
    mrow[1] = nm1;

#pragma unroll
    for (int na = 0; na < 8; na++) {
      O[na][0] *= corr0;
      O[na][1] *= corr0;
      O[na][2] *= corr1;
      O[na][3] *= corr1;
      Ps[(pr + g) * AS + na * 8 + 2 * t] = f2tf_f(s[na][0]);
      Ps[(pr + g) * AS + na * 8 + 2 * t + 1] = f2tf_f(s[na][1]);
      Ps[(pr + g + 8) * AS + na * 8 + 2 * t] = f2tf_f(s[na][2]);
      Ps[(pr + g + 8) * AS + na * 8 + 2 * t + 1] = f2tf_f(s[na][3]);
    }
    __syncwarp();

    // O += P @ V
#pragma unroll
    for (int ks = 0; ks < 8; ks++) {
      const uint32_t a0 = __float_as_uint(Ps[(pr + g) * AS + ks * 8 + t]);
      const uint32_t a1 = __float_as_uint(Ps[(pr + g + 8) * AS + ks * 8 + t]);
      const uint32_t a2 = __float_as_uint(Ps[(pr + g) * AS + ks * 8 + t + 4]);
      const uint32_t a3 =
          __float_as_uint(Ps[(pr + g + 8) * AS + ks * 8 + t + 4]);
#pragma unroll
      for (int na = 0; na < 8; na++) {
        const uint32_t b0 = __float_as_uint(Vb[(ks * 8 + t) * AS + na * 8 + g]);
        const uint32_t b1 =
            __float_as_uint(Vb[(ks * 8 + t + 4) * AS + na * 8 + g]);
        mma_tf32(O[na], a0, a1, a2, a3, b0, b1);
      }
    }
    __syncthreads();  // compute done before next prefetch overwrites buf
  }

  // Epilogue: normalize, round to tf32 (out-proj A operand), write [B, L, D]
  const int b = bh / H_;
  const int h = bh % H_;
  const float inv0 = 1.f / lrow[0];
  const float inv1 = 1.f / lrow[1];
  const int r0 = q0 + pr + g;
  const int r1 = r0 + 8;
#pragma unroll
  for (int na = 0; na < 8; na++) {
    const int dh = na * 8 + 2 * t;
    float2 v;
    v.x = f2tf_f(O[na][0] * inv0);
    v.y = f2tf_f(O[na][1] * inv0);
    *(float2*)&g_ctx[((size_t)b * L_ + r0) * D_ + h * DH_ + dh] = v;
    v.x = f2tf_f(O[na][2] * inv1);
    v.y = f2tf_f(O[na][3] * inv1);
    *(float2*)&g_ctx[((size_t)b * L_ + r1) * D_ + h * DH_ + dh] = v;
  }
}

#define ATT_SMEM_BYTES ((2 * 128 * AS + 4 * 64 * AS) * 4)  // 139264

// ---------------------------------------------------------------------------
extern "C" void kernel_launch(void* const* d_in, const int* in_sizes, int n_in,
                              void* d_out, int out_size) {
  const float* X   = (const float*)d_in[0];
  const float* Wq  = (const float*)d_in[1];
  const float* Wk  = (const float*)d_in[2];
  const float* Wv  = (const float*)d_in[3];
  const float* Wo  = (const float*)d_in[4];
  const float* bo  = (const float*)d_in[5];
  const float* Kbg = (const float*)d_in[6];
  const float* Vbg = (const float*)d_in[7];
  float* out = (float*)d_out;

  // 0) Prep: round/prescale operands once
  prep_round<<<5120, 256>>>(X, Kbg, Vbg);
  transpose_w<<<dim3(D_ / 32, D_ / 32, 4), dim3(32, 8)>>>(Wq, Wk, Wv, Wo);

  // 1) Merged QKV projection
  cudaFuncSetAttribute(gemm_qkv, cudaFuncAttributeMaxDynamicSharedMemorySize,
                       GM_SMEM_BYTES);
  gemm_qkv<<<dim3(15, 32), 256, GM_SMEM_BYTES>>>();

  // 2) Flash attention
  cudaFuncSetAttribute(attn_mma, cudaFuncAttributeMaxDynamicSharedMemorySize,
                       ATT_SMEM_BYTES);
  attn_mma<<<dim3(L_ / 128, BH_), 256, ATT_SMEM_BYTES>>>();

  // 3) Output projection + bias
  cudaFuncSetAttribute(gemm_out, cudaFuncAttributeMaxDynamicSharedMemorySize,
                       GM_SMEM_BYTES);
  gemm_out<<<dim3(5, 32), 256, GM_SMEM_BYTES>>>(bo, out);
}

// round 10
// speedup vs baseline: 1.4300x; 1.4300x over previous
#include <cuda_runtime.h>
#include <cstdint>

#define B_   4
#define L_   1024
#define D_   1280
#define H_   20
#define DH_  64
#define BH_  80
#define ALPHA_ 0.48f
#define LOG2E_ 1.44269504088896340736f
#define QSCALE_ (0.125f * LOG2E_)   // fold 1/sqrt(dh) and log2e into Q

// ---------------------------------------------------------------------------
// Scratch (device globals — no allocation allowed)
// ---------------------------------------------------------------------------
__device__ float g_q[BH_ * L_ * DH_];     // tf32-rounded, QSCALE folded
__device__ float g_k[BH_ * L_ * DH_];     // tf32-rounded
__device__ float g_v[BH_ * L_ * DH_];     // tf32-rounded
__device__ float g_kbg[BH_ * L_ * DH_];   // tf32(ALPHA*Kbg)
__device__ float g_vbg[BH_ * L_ * DH_];   // tf32(ALPHA*Vbg)
__device__ float g_xr[B_ * L_ * D_];      // tf32(X)
__device__ float g_ctx[B_ * L_ * D_];     // tf32-rounded context
__device__ float g_wt[4 * D_ * D_];       // tf32(W^T)  [N,K] row-major

// ---------------------------------------------------------------------------
// Helpers (baseline PTX only)
// ---------------------------------------------------------------------------
__device__ __forceinline__ uint32_t smem_to_u32(const void* p) {
  uint32_t a;
  asm("{ .reg .u64 t; cvta.to.shared.u64 t, %1; cvt.u32.u64 %0, t; }"
      : "=r"(a) : "l"(p));
  return a;
}
__device__ __forceinline__ float f2tf_f(float x) {
  uint32_t r;
  asm("cvt.rna.tf32.f32 %0, %1;" : "=r"(r) : "f"(x));
  return __uint_as_float(r);
}
__device__ __forceinline__ float ex2(float x) {
  float r;
  asm("ex2.approx.ftz.f32 %0, %1;" : "=f"(r) : "f"(x));
  return r;
}
__device__ __forceinline__ void mma_tf32(float* c, uint32_t a0, uint32_t a1,
                                         uint32_t a2, uint32_t a3, uint32_t b0,
                                         uint32_t b1) {
  asm volatile(
      "mma.sync.aligned.m16n8k8.row.col.f32.tf32.tf32.f32 "
      "{%0,%1,%2,%3}, {%4,%5,%6,%7}, {%8,%9}, {%0,%1,%2,%3};"
      : "+f"(c[0]), "+f"(c[1]), "+f"(c[2]), "+f"(c[3])
      : "r"(a0), "r"(a1), "r"(a2), "r"(a3), "r"(b0), "r"(b1));
}
__device__ __forceinline__ void cp_async16(uint32_t saddr, const void* g) {
  asm volatile("cp.async.cg.shared.global [%0], [%1], 16;" ::"r"(saddr),
               "l"(g));
}
#define CP_COMMIT() asm volatile("cp.async.commit_group;")
#define CP_WAIT(n) asm volatile("cp.async.wait_group %0;" ::"n"(n))

// ---------------------------------------------------------------------------
// Prep 1: round X -> g_xr; prescale+round bg K/V.
// ---------------------------------------------------------------------------
__global__ __launch_bounds__(256) void prep_round(const float* __restrict__ X,
                                                  const float* __restrict__ Kbg,
                                                  const float* __restrict__ Vbg) {
  const size_t i = ((size_t)blockIdx.x * 256 + threadIdx.x) * 4;
  {
    const float4 v = *(const float4*)&X[i];
    float4 o;
    o.x = f2tf_f(v.x); o.y = f2tf_f(v.y); o.z = f2tf_f(v.z); o.w = f2tf_f(v.w);
    *(float4*)&g_xr[i] = o;
  }
  {
    const float4 v = *(const float4*)&Kbg[i];
    float4 o;
    o.x = f2tf_f(v.x * ALPHA_); o.y = f2tf_f(v.y * ALPHA_);
    o.z = f2tf_f(v.z * ALPHA_); o.w = f2tf_f(v.w * ALPHA_);
    *(float4*)&g_kbg[i] = o;
  }
  {
    const float4 v = *(const float4*)&Vbg[i];
    float4 o;
    o.x = f2tf_f(v.x * ALPHA_); o.y = f2tf_f(v.y * ALPHA_);
    o.z = f2tf_f(v.z * ALPHA_); o.w = f2tf_f(v.w * ALPHA_);
    *(float4*)&g_vbg[i] = o;
  }
}

// ---------------------------------------------------------------------------
// Prep 2: transpose + round weights: g_wt[z][n][k] = tf32(W_z[k][n])
// ---------------------------------------------------------------------------
__global__ void transpose_w(const float* __restrict__ Wq,
                            const float* __restrict__ Wk,
                            const float* __restrict__ Wv,
                            const float* __restrict__ Wo) {
  __shared__ float t[32][33];
  const float* src;
  switch (blockIdx.z) {
    case 0: src = Wq; break;
    case 1: src = Wk; break;
    case 2: src = Wv; break;
    default: src = Wo; break;
  }
  float* dst = g_wt + (size_t)blockIdx.z * D_ * D_;
  const int x0 = blockIdx.x * 32;  // n
  const int y0 = blockIdx.y * 32;  // k
  const int tx = threadIdx.x;
#pragma unroll
  for (int i = threadIdx.y; i < 32; i += 8)
    t[i][tx] = src[(size_t)(y0 + i) * D_ + x0 + tx];
  __syncthreads();
#pragma unroll
  for (int i = threadIdx.y; i < 32; i += 8)
    dst[(size_t)(x0 + i) * D_ + y0 + tx] = f2tf_f(t[tx][i]);
}

// ---------------------------------------------------------------------------
// tf32 mma GEMM. Block 128 thr (4 warps, 2x2), block tile 128x128,
// warp tile 64x64, K-chunk 32, cp.async double buffer. 2 CTAs/SM.
// MODE 0: merged QKV -> head layout.  MODE 1: out-proj -> row-major + bias.
// ---------------------------------------------------------------------------
#define GM_STR 36
#define GM_TBUF (128 * GM_STR)                  // 4608 floats per tile buffer
#define GM_SMEM_BYTES (4 * GM_TBUF * 4)         // 73728

template <int MODE>
__device__ __forceinline__ void gemm_body(const float* __restrict__ A,
                                          const float* __restrict__ Bm,
                                          const float* __restrict__ bo,
                                          float* __restrict__ dstArg) {
  extern __shared__ float sm[];
  float* Abuf[2] = {sm, sm + GM_TBUF};
  float* Bbuf[2] = {sm + 2 * GM_TBUF, sm + 3 * GM_TBUF};
  const uint32_t sbase = smem_to_u32(sm);
  const uint32_t aoff[2] = {0u, (uint32_t)(GM_TBUF * 4)};
  const uint32_t boff[2] = {(uint32_t)(2 * GM_TBUF * 4),
                            (uint32_t)(3 * GM_TBUF * 4)};

  const int tid = threadIdx.x;
  const int wid = tid >> 5, lid = tid & 31;
  const int wm = wid >> 1, wn = wid & 1;  // 2 x 2 warps
  const int g = lid >> 2, t = lid & 3;
  const int m0 = blockIdx.y * 128;

  const int ldr = tid >> 3;       // 0..15
  const int ldc = (tid & 7) * 4;  // 0..28

  float c[4][8][4];
#pragma unroll
  for (int ma = 0; ma < 4; ma++)
#pragma unroll
    for (int na = 0; na < 8; na++)
#pragma unroll
      for (int k = 0; k < 4; k++) c[ma][na][k] = 0.f;

  // prologue prefetch chunk 0
#pragma unroll
  for (int i = 0; i < 8; i++) {
    const int r = i * 16 + ldr;
    cp_async16(sbase + aoff[0] + ((r * GM_STR + ldc) << 2),
               &A[(size_t)(m0 + r) * D_ + ldc]);
    cp_async16(sbase + boff[0] + ((r * GM_STR + ldc) << 2),
               &Bm[(size_t)r * D_ + ldc]);
  }
  CP_COMMIT();

  for (int ch = 0; ch < 40; ch++) {
    const int buf = ch & 1;
    if (ch + 1 < 40) {
      const int nb = 1 - buf;
      const int k0 = (ch + 1) * 32;
#pragma unroll
      for (int i = 0; i < 8; i++) {
        const int r = i * 16 + ldr;
        cp_async16(sbase + aoff[nb] + ((r * GM_STR + ldc) << 2),
                   &A[(size_t)(m0 + r) * D_ + k0 + ldc]);
        cp_async16(sbase + boff[nb] + ((r * GM_STR + ldc) << 2),
                   &Bm[(size_t)r * D_ + k0 + ldc]);
      }
      CP_COMMIT();
      CP_WAIT(1);
    } else {
      CP_WAIT(0);
    }
    __syncthreads();

    const float* Ab = Abuf[buf];
    const float* Bb = Bbuf[buf];
#pragma unroll
    for (int ks = 0; ks < 4; ks++) {
      uint32_t af[4][4];
#pragma unroll
      for (int ma = 0; ma < 4; ma++) {
        const int row = wm * 64 + ma * 16;
        af[ma][0] = __float_as_uint(Ab[(row + g) * GM_STR + ks * 8 + t]);
        af[ma][1] = __float_as_uint(Ab[(row + g + 8) * GM_STR + ks * 8 + t]);
        af[ma][2] = __float_as_uint(Ab[(row + g) * GM_STR + ks * 8 + t + 4]);
        af[ma][3] = __float_as_uint(Ab[(row + g + 8) * GM_STR + ks * 8 + t + 4]);
      }
      uint32_t bf[8][2];
#pragma unroll
      for (int na = 0; na < 8; na++) {
        const int col = wn * 64 + na * 8 + g;
        bf[na][0] = __float_as_uint(Bb[col * GM_STR + ks * 8 + t]);
        bf[na][1] = __float_as_uint(Bb[col * GM_STR + ks * 8 + t + 4]);
      }
#pragma unroll
      for (int ma = 0; ma < 4; ma++)
#pragma unroll
        for (int na = 0; na < 8; na++)
          mma_tf32(c[ma][na], af[ma][0], af[ma][1], af[ma][2], af[ma][3],
                   bf[na][0], bf[na][1]);
    }
    __syncthreads();
  }

  // epilogue
  if (MODE == 0) {
    const int gn0 = blockIdx.x * 128;
    const int z = gn0 / D_;
    const int nloc0 = gn0 % D_;
    float* dst = (z == 0) ? g_q : (z == 1) ? g_k : g_v;
    const float sc = (z == 0) ? QSCALE_ : 1.f;
#pragma unroll
    for (int ma = 0; ma < 4; ma++) {
      const int r0 = m0 + wm * 64 + ma * 16 + g;
      const int r1 = r0 + 8;
      const int b0i = r0 >> 10, l0i = r0 & 1023;
      const int b1i = r1 >> 10, l1i = r1 & 1023;
#pragma unroll
      for (int na = 0; na < 8; na++) {
        const int col = nloc0 + wn * 64 + na * 8 + 2 * t;
        const int h = col >> 6, dh = col & 63;
        float2 v;
        v.x = f2tf_f(c[ma][na][0] * sc);
        v.y = f2tf_f(c[ma][na][1] * sc);
        *(float2*)&dst[((size_t)(b0i * H_ + h) * L_ + l0i) * DH_ + dh] = v;
        v.x = f2tf_f(c[ma][na][2] * sc);
        v.y = f2tf_f(c[ma][na][3] * sc);
        *(float2*)&dst[((size_t)(b1i * H_ + h) * L_ + l1i) * DH_ + dh] = v;
      }
    }
  } else {
    const int n0 = blockIdx.x * 128;
#pragma unroll
    for (int ma = 0; ma < 4; ma++) {
      const int r0 = m0 + wm * 64 + ma * 16 + g;
      const int r1 = r0 + 8;
#pragma unroll
      for (int na = 0; na < 8; na++) {
        const int col = n0 + wn * 64 + na * 8 + 2 * t;
        const float2 bias = *(const float2*)&bo[col];
        float2 v;
        v.x = c[ma][na][0] + bias.x;
        v.y = c[ma][na][1] + bias.y;
        *(float2*)&dstArg[(size_t)r0 * D_ + col] = v;
        v.x = c[ma][na][2] + bias.x;
        v.y = c[ma][na][3] + bias.y;
        *(float2*)&dstArg[(size_t)r1 * D_ + col] = v;
      }
    }
  }
}

// grid (30, 32): x covers 3840 output cols (Q|K|V)
__global__ __launch_bounds__(128, 2) void gemm_qkv() {
  const int gn0 = blockIdx.x * 128;
  const int z = gn0 / D_;
  const float* Bm = g_wt + (size_t)z * D_ * D_ + (size_t)(gn0 % D_) * D_;
  gemm_body<0>(g_xr, Bm, nullptr, nullptr);
}

// grid (10, 32)
__global__ __launch_bounds__(128, 2) void gemm_out(const float* __restrict__ bo,
                                                   float* __restrict__ out) {
  const float* Bm = g_wt + (size_t)3 * D_ * D_ + (size_t)(blockIdx.x * 128) * D_;
  gemm_body<1>(g_ctx, Bm, bo, out);
}

// ---------------------------------------------------------------------------
// Flash attention, tf32 mma. Block 128 thr (4 warps), Q tile 64 (16/warp),
// KV tile 64. Q fragments cached in registers. K single-buffered (prefetch
// overlaps softmax+PV), V double-buffered. 3 CTAs/SM. grid = (16, 80).
// smem: Ps(64x68) + Ks(64x68) + Vs0 + Vs1 = 69632 B
// FIX vs round 8: KV tile loads are 8 iterations (full 64 rows), not 4.
// ---------------------------------------------------------------------------
#define AS 68
#define ATT_ROWB (64 * AS)                       // floats per 64x68 array
#define ATT_SMEM_BYTES (4 * ATT_ROWB * 4)        // 69632

__global__ __launch_bounds__(128, 3) void attn_mma() {
  extern __shared__ float sm[];
  float* Ps = sm;                       // also Q staging before the loop
  float* Ks = sm + ATT_ROWB;
  float* Vs[2] = {sm + 2 * ATT_ROWB, sm + 3 * ATT_ROWB};
  const uint32_t sbase = smem_to_u32(sm);
  const uint32_t koff = (uint32_t)(ATT_ROWB * 4);
  const uint32_t voff[2] = {(uint32_t)(2 * ATT_ROWB * 4),
                            (uint32_t)(3 * ATT_ROWB * 4)};

  const int tid = threadIdx.x;
  const int wid = tid >> 5, lid = tid & 31;
  const int g = lid >> 2, t = lid & 3;
  const int bh = blockIdx.y;
  const int q0 = blockIdx.x * 64;
  const int pr = wid * 16;  // warp's Q/P row base

  const float* qptr = g_q + (size_t)bh * L_ * DH_ + (size_t)q0 * DH_;
  const float* kfr = g_k + (size_t)bh * L_ * DH_;
  const float* vfr = g_v + (size_t)bh * L_ * DH_;
  const float* kbg = g_kbg + (size_t)bh * L_ * DH_;
  const float* vbg = g_vbg + (size_t)bh * L_ * DH_;

  // prefetch KV tile 0 (K -> Ks, V -> Vs[0]); full 64x64 tile = 1024 float4
#pragma unroll
  for (int i = 0; i < 8; i++) {
    const int id4 = i * 128 + tid;
    const int r = id4 >> 4, cc = (id4 & 15) * 4;
    cp_async16(sbase + koff + ((r * AS + cc) << 2), &kfr[(size_t)r * DH_ + cc]);
    cp_async16(sbase + voff[0] + ((r * AS + cc) << 2),
               &vfr[(size_t)r * DH_ + cc]);
  }
  CP_COMMIT();

  // stage Q tile into Ps, then extract fragments into registers
#pragma unroll
  for (int i = 0; i < 8; i++) {
    const int idx = i * 128 + tid;
    const int r = idx >> 4, cc = (idx & 15) * 4;
    *(float4*)&Ps[r * AS + cc] = *(const float4*)&qptr[(size_t)r * DH_ + cc];
  }
  __syncthreads();
  uint32_t qf[8][4];
#pragma unroll
  for (int ks = 0; ks < 8; ks++) {
    qf[ks][0] = __float_as_uint(Ps[(pr + g) * AS + ks * 8 + t]);
    qf[ks][1] = __float_as_uint(Ps[(pr + g + 8) * AS + ks * 8 + t]);
    qf[ks][2] = __float_as_uint(Ps[(pr + g) * AS + ks * 8 + t + 4]);
    qf[ks][3] = __float_as_uint(Ps[(pr + g + 8) * AS + ks * 8 + t + 4]);
  }
  // No barrier needed before later P stores: each warp only rewrites its own
  // rows [pr, pr+16), which only it read during extraction.

  float mrow[2] = {-1e30f, -1e30f};
  float lrow[2] = {0.f, 0.f};
  float O[8][4];
#pragma unroll
  for (int na = 0; na < 8; na++)
#pragma unroll
    for (int k = 0; k < 4; k++) O[na][k] = 0.f;

  for (int it = 0; it < 32; it++) {
    const int vb = it & 1;
    CP_WAIT(0);
    __syncthreads();  // K_it / V_it visible; all warps past PV of it-1

    // S = Q @ K^T : warp rows [pr, pr+16), cols [0,64)
    float s[8][4];
#pragma unroll
    for (int na = 0; na < 8; na++)
#pragma unroll
      for (int k = 0; k < 4; k++) s[na][k] = 0.f;

#pragma unroll
    for (int ks = 0; ks < 8; ks++) {
#pragma unroll
      for (int na = 0; na < 8; na++) {
        const uint32_t b0 = __float_as_uint(Ks[(na * 8 + g) * AS + ks * 8 + t]);
        const uint32_t b1 =
            __float_as_uint(Ks[(na * 8 + g) * AS + ks * 8 + t + 4]);
        mma_tf32(s[na], qf[ks][0], qf[ks][1], qf[ks][2], qf[ks][3], b0, b1);
      }
    }
    __syncthreads();  // all warps done reading Ks -> safe to overwrite

    // prefetch K_{it+1} into Ks and V_{it+1} into the other V buffer;
    // overlaps softmax + PV below. Full 64x64 tiles.
    if (it + 1 < 32) {
      const int nt = it + 1;
      const float* kp = (nt < 16) ? kfr + (size_t)nt * 64 * DH_
                                  : kbg + (size_t)(nt - 16) * 64 * DH_;
      const float* vp = (nt < 16) ? vfr + (size_t)nt * 64 * DH_
                                  : vbg + (size_t)(nt - 16) * 64 * DH_;
#pragma unroll
      for (int i = 0; i < 8; i++) {
        const int id4 = i * 128 + tid;
        const int r = id4 >> 4, cc = (id4 & 15) * 4;
        cp_async16(sbase + koff + ((r * AS + cc) << 2),
                   &kp[(size_t)r * DH_ + cc]);
        cp_async16(sbase + voff[1 - vb] + ((r * AS + cc) << 2),
                   &vp[(size_t)r * DH_ + cc]);
      }
      CP_COMMIT();
    }

    // Online softmax (log2 domain)
    float mx0 = -1e30f, mx1 = -1e30f;
#pragma unroll
    for (int na = 0; na < 8; na++) {
      mx0 = fmaxf(mx0, fmaxf(s[na][0], s[na][1]));
      mx1 = fmaxf(mx1, fmaxf(s[na][2], s[na][3]));
    }
    mx0 = fmaxf(mx0, __shfl_xor_sync(0xffffffffu, mx0, 1));
    mx0 = fmaxf(mx0, __shfl_xor_sync(0xffffffffu, mx0, 2));
    mx1 = fmaxf(mx1, __shfl_xor_sync(0xffffffffu, mx1, 1));
    mx1 = fmaxf(mx1, __shfl_xor_sync(0xffffffffu, mx1, 2));

    const float nm0 = fmaxf(mrow[0], mx0);
    const float nm1 = fmaxf(mrow[1], mx1);
    const float corr0 = ex2(mrow[0] - nm0);
    const float corr1 = ex2(mrow[1] - nm1);

    float sum0 = 0.f, sum1 = 0.f;
#pragma unroll
    for (int na = 0; na < 8; na++) {
      s[na][0] = ex2(s[na][0] - nm0);
      s[na][1] = ex2(s[na][1] - nm0);
      s[na][2] = ex2(s[na][2] - nm1);
      s[na][3] = ex2(s[na][3] - nm1);
      sum0 += s[na][0] + s[na][1];
      sum1 += s[na][2] + s[na][3];
    }
    sum0 += __shfl_xor_sync(0xffffffffu, sum0, 1);
    sum0 += __shfl_xor_sync(0xffffffffu, sum0, 2);
    sum1 += __shfl_xor_sync(0xffffffffu, sum1, 1);
    sum1 += __shfl_xor_sync(0xffffffffu, sum1, 2);

    lrow[0] = lrow[0] * corr0 + sum0;
    lrow[1] = lrow[1] * corr1 + sum1;
    mrow[0] = nm0;
    mrow[1] = nm1;

#pragma unroll
    for (int na = 0; na < 8; na++) {
      O[na][0] *= corr0;
      O[na][1] *= corr0;
      O[na][2] *= corr1;
      O[na][3] *= corr1;
      Ps[(pr + g) * AS + na * 8 + 2 * t] = f2tf_f(s[na][0]);
      Ps[(pr + g) * AS + na * 8 + 2 * t + 1] = f2tf_f(s[na][1]);
      Ps[(pr + g + 8) * AS + na * 8 + 2 * t] = f2tf_f(s[na][2]);
      Ps[(pr + g + 8) * AS + na * 8 + 2 * t + 1] = f2tf_f(s[na][3]);
    }
    __syncwarp();

    // O += P @ V  (V buffer vb; prefetch writes go to 1-vb)
    const float* Vb = Vs[vb];
#pragma unroll
    for (int ks = 0; ks < 8; ks++) {
      const uint32_t a0 = __float_as_uint(Ps[(pr + g) * AS + ks * 8 + t]);
      const uint32_t a1 = __float_as_uint(Ps[(pr + g + 8) * AS + ks * 8 + t]);
      const uint32_t a2 = __float_as_uint(Ps[(pr + g) * AS + ks * 8 + t + 4]);
      const uint32_t a3 =
          __float_as_uint(Ps[(pr + g + 8) * AS + ks * 8 + t + 4]);
#pragma unroll
      for (int na = 0; na < 8; na++) {
        const uint32_t b0 = __float_as_uint(Vb[(ks * 8 + t) * AS + na * 8 + g]);
        const uint32_t b1 =
            __float_as_uint(Vb[(ks * 8 + t + 4) * AS + na * 8 + g]);
        mma_tf32(O[na], a0, a1, a2, a3, b0, b1);
      }
    }
  }

  // Epilogue: normalize, round to tf32 (out-proj A operand), write [B, L, D]
  const int b = bh / H_;
  const int h = bh % H_;
  const float inv0 = 1.f / lrow[0];
  const float inv1 = 1.f / lrow[1];
  const int r0 = q0 + pr + g;
  const int r1 = r0 + 8;
#pragma unroll
  for (int na = 0; na < 8; na++) {
    const int dh = na * 8 + 2 * t;
    float2 v;
    v.x = f2tf_f(O[na][0] * inv0);
    v.y = f2tf_f(O[na][1] * inv0);
    *(float2*)&g_ctx[((size_t)b * L_ + r0) * D_ + h * DH_ + dh] = v;
    v.x = f2tf_f(O[na][2] * inv1);
    v.y = f2tf_f(O[na][3] * inv1);
    *(float2*)&g_ctx[((size_t)b * L_ + r1) * D_ + h * DH_ + dh] = v;
  }
}

// ---------------------------------------------------------------------------
extern "C" void kernel_launch(void* const* d_in, const int* in_sizes, int n_in,
                              void* d_out, int out_size) {
  const float* X   = (const float*)d_in[0];
  const float* Wq  = (const float*)d_in[1];
  const float* Wk  = (const float*)d_in[2];
  const float* Wv  = (const float*)d_in[3];
  const float* Wo  = (const float*)d_in[4];
  const float* bo  = (const float*)d_in[5];
  const float* Kbg = (const float*)d_in[6];
  const float* Vbg = (const float*)d_in[7];
  float* out = (float*)d_out;

  // 0) Prep: round/prescale operands once
  prep_round<<<5120, 256>>>(X, Kbg, Vbg);
  transpose_w<<<dim3(D_ / 32, D_ / 32, 4), dim3(32, 8)>>>(Wq, Wk, Wv, Wo);

  // 1) Merged QKV projection
  cudaFuncSetAttribute(gemm_qkv, cudaFuncAttributeMaxDynamicSharedMemorySize,
                       GM_SMEM_BYTES);
  gemm_qkv<<<dim3(30, 32), 128, GM_SMEM_BYTES>>>();

  // 2) Flash attention
  cudaFuncSetAttribute(attn_mma, cudaFuncAttributeMaxDynamicSharedMemorySize,
                       ATT_SMEM_BYTES);
  attn_mma<<<dim3(L_ / 64, BH_), 128, ATT_SMEM_BYTES>>>();

  // 3) Output projection + bias
  cudaFuncSetAttribute(gemm_out, cudaFuncAttributeMaxDynamicSharedMemorySize,
                       GM_SMEM_BYTES);
  gemm_out<<<dim3(10, 32), 128, GM_SMEM_BYTES>>>(bo, out);
}